// round 5
// baseline (speedup 1.0000x reference)
#include <cuda_runtime.h>
#include <cuda_bf16.h>
#include <cstdint>

// Blur_82471962018173: depthwise separable 4x4 FIR ([1,3,3,1]/4 per axis),
// input (4,128,513,513) f32, pad=1 both sides, output (4,128,512,512) f32.
//
// R5: cp.async ring pipeline (as R4) with: occupancy raised to 12 blocks/SM
// (launch_bounds reg cap), thread-invariant cp.async predicates hoisted out
// of the row loop, rolling global row pointer, ROWS=128 (halo 2.3%).

#define W_IN   513
#define W_OUT  512
#define ROWS   128
#define NT     128
#define DEPTH  6
#define SLOTS  8
#define SSTR   520   // floats per ring slot (515 used)

__device__ __forceinline__ void cp4(uint32_t dst, const float* src, int sz) {
    asm volatile("cp.async.ca.shared.global [%0], [%1], 4, %2;"
                 :: "r"(dst), "l"(src), "r"(sz));
}

__global__ __launch_bounds__(NT, 12)
void blur_kernel(const float* __restrict__ in, float* __restrict__ out) {
    __shared__ float ring[SLOTS][SSTR];   // ring[s][i] holds input x = i-1

    const int nc = blockIdx.z;
    const int y0 = blockIdx.y * ROWS;
    const int t  = threadIdx.x;
    const int x0 = t << 2;                // output cols x0..x0+3

    const float* __restrict__ inp  = in  + (size_t)nc * (W_IN  * W_IN);
    float*       __restrict__ outp = out + (size_t)nc * (W_OUT * W_OUT);

    // thread-invariant column validity / offsets (hoisted out of row loop)
    const int  c0 = t - 1;                        // main cols: c0 + j*NT, j=0..3
    const int  sz0 = (t == 0) ? 0 : 4;            // only i==0 (x=-1) invalid
    const bool edge   = (t < 3);                  // i = 512+t -> x = 511..513
    const int  sz_e   = (t < 2) ? 4 : 0;          // x=513 invalid
    const int  ce     = 511 + t;

    const uint32_t sring = (uint32_t)__cvta_generic_to_shared(&ring[0][0]);

    // rolling global row pointer for yy = y0 - 1 + r
    const float* rp = inp + (size_t)(y0 - 1) * W_IN;

    auto issue_row = [&](int r) {
        const int yy = y0 - 1 + r;
        const bool rowok = ((unsigned)yy < (unsigned)W_IN);   // warp-uniform
        const uint32_t sb = sring + (uint32_t)(r & (SLOTS - 1)) * (SSTR * 4);
        const float* rr = rowok ? (rp + (size_t)r * W_IN) : inp;
        cp4(sb + (t + 0 * NT) * 4, rr + c0 + 0 * NT, rowok ? sz0 : 0);
        cp4(sb + (t + 1 * NT) * 4, rr + c0 + 1 * NT, rowok ? 4 : 0);
        cp4(sb + (t + 2 * NT) * 4, rr + c0 + 2 * NT, rowok ? 4 : 0);
        cp4(sb + (t + 3 * NT) * 4, rr + c0 + 3 * NT, rowok ? 4 : 0);
        if (edge)
            cp4(sb + (512 + t) * 4, rr + ce, rowok ? sz_e : 0);
    };

    // prologue: fill the pipe with DEPTH rows
    #pragma unroll
    for (int j = 0; j < DEPTH; ++j) {
        issue_row(j);
        asm volatile("cp.async.commit_group;");
    }

    float4 hw[4];                              // rolling h-filtered rows
    float* op = outp + (size_t)y0 * W_OUT + x0;

    #pragma unroll 4
    for (int r = 0; r < ROWS + 3; ++r) {
        if (r + DEPTH < ROWS + 3) issue_row(r + DEPTH);
        asm volatile("cp.async.commit_group;");           // empty group on tail
        asm volatile("cp.async.wait_group %0;" :: "n"(DEPTH - 1));
        __syncthreads();                                  // row r visible to all

        const float* s = ring[r & (SLOTS - 1)];
        const float4 A = *(const float4*)(s + x0);        // x = x0-1 .. x0+2
        const float4 B = *(const float4*)(s + x0 + 4);    // x = x0+3 .. x0+6
        float4 hc;
        hc.x = 0.25f * (A.x + A.w) + 0.75f * (A.y + A.z);
        hc.y = 0.25f * (A.y + B.x) + 0.75f * (A.z + A.w);
        hc.z = 0.25f * (A.z + B.y) + 0.75f * (A.w + B.x);
        hc.w = 0.25f * (A.w + B.z) + 0.75f * (B.x + B.y);
        hw[r & 3] = hc;

        if (r >= 3) {
            const float4 a = hw[(r - 3) & 3];
            const float4 b = hw[(r - 2) & 3];
            const float4 c = hw[(r - 1) & 3];
            float4 o;
            o.x = 0.25f * (a.x + hc.x) + 0.75f * (b.x + c.x);
            o.y = 0.25f * (a.y + hc.y) + 0.75f * (b.y + c.y);
            o.z = 0.25f * (a.z + hc.z) + 0.75f * (b.z + c.z);
            o.w = 0.25f * (a.w + hc.w) + 0.75f * (b.w + c.w);
            *(float4*)(op + (size_t)(r - 3) * W_OUT) = o;
        }
    }
}

extern "C" void kernel_launch(void* const* d_in, const int* in_sizes, int n_in,
                              void* d_out, int out_size) {
    const float* in = (const float*)d_in[0];   // (4,128,513,513) f32
    float* out = (float*)d_out;                // (4,128,512,512) f32
    dim3 grid(1, W_OUT / ROWS, 4 * 128);       // 4 row-strips x 512 planes
    blur_kernel<<<grid, NT>>>(in, out);
}